// round 12
// baseline (speedup 1.0000x reference)
#include <cuda_runtime.h>
#include <cuda_fp16.h>
#include <cstdint>

#define BH_  64
#define LQ_  1024
#define LK_  1024
#define DD_  64
#define TQ_  32
#define NT   256
#define PSTR_H 2064          // S/P row bytes (1032 fp16; 129×16B -> conflict-free ldmatrix)
#define KROWB  144           // K/V smem row bytes (72 fp16)
#define KTROWS 64            // K/V tile rows
#define OFF_KV (TQ_*PSTR_H)            // 66048
#define KVHALF (KTROWS*KROWB)          // 9216
#define KVBUFSZ (2*KVHALF)             // 18432 (K: hi+lo)
#define OFF_Q  (OFF_KV + 2*KVBUFSZ)    // 102912
#define QPLANE (TQ_*KROWB)             // 4608 (x2 = 9216 = one V tile: reused as vbuf0)
#define SM_TOTAL (OFF_Q + 2*QPLANE)    // 112128 -> 2 CTAs/SM

__device__ __half g_QH[BH_*LQ_*DD_];
__device__ __half g_QL[BH_*LQ_*DD_];
__device__ __half g_KH[BH_*LK_*DD_];
__device__ __half g_KL[BH_*LK_*DD_];
__device__ __half g_VH[BH_*LK_*DD_];

__device__ __forceinline__ uint32_t s2u(const void* p) {
    uint32_t a;
    asm("{.reg .u64 t; cvta.to.shared.u64 t, %1; cvt.u32.u64 %0, t;}" : "=r"(a) : "l"(p));
    return a;
}
__device__ __forceinline__ void lm4(uint32_t* r, uint32_t addr) {
    asm volatile("ldmatrix.sync.aligned.m8n8.x4.shared.b16 {%0,%1,%2,%3}, [%4];"
                 : "=r"(r[0]), "=r"(r[1]), "=r"(r[2]), "=r"(r[3]) : "r"(addr));
}
__device__ __forceinline__ void lm4t(uint32_t* r, uint32_t addr) {
    asm volatile("ldmatrix.sync.aligned.m8n8.x4.trans.shared.b16 {%0,%1,%2,%3}, [%4];"
                 : "=r"(r[0]), "=r"(r[1]), "=r"(r[2]), "=r"(r[3]) : "r"(addr));
}
__device__ __forceinline__ void mma16816(float* c, const uint32_t* a, uint32_t b0, uint32_t b1) {
    asm volatile("mma.sync.aligned.m16n8k16.row.col.f32.f16.f16.f32 "
                 "{%0,%1,%2,%3}, {%4,%5,%6,%7}, {%8,%9}, {%0,%1,%2,%3};"
                 : "+f"(c[0]), "+f"(c[1]), "+f"(c[2]), "+f"(c[3])
                 : "r"(a[0]), "r"(a[1]), "r"(a[2]), "r"(a[3]), "r"(b0), "r"(b1));
}
__device__ __forceinline__ void cp16(char* dst, const void* src) {
    uint32_t s = s2u(dst);
    asm volatile("cp.async.cg.shared.global [%0], [%1], 16;" :: "r"(s), "l"(src));
}
__device__ __forceinline__ void cp_commit() { asm volatile("cp.async.commit_group;"); }
__device__ __forceinline__ void cp_wait0() { asm volatile("cp.async.wait_group 0;"); }
__device__ __forceinline__ void cp_wait1() { asm volatile("cp.async.wait_group 1;"); }

__device__ __forceinline__ uint32_t pack_hi2(float a, float b) {
    __half2 h = __floats2half2_rn(a, b);
    return *(uint32_t*)&h;
}
__device__ __forceinline__ uint32_t pack_lo2(float a, float b) {
    float ra = a - __half2float(__float2half_rn(a));
    float rb = b - __half2float(__float2half_rn(b));
    __half2 l = __floats2half2_rn(ra, rb);
    return *(uint32_t*)&l;
}

// ---------------- kernel 1: fp32 -> fp16 splits (Q/K hi+lo, V hi only) ----------------
__global__ void __launch_bounds__(256) cvt_kernel(const float* __restrict__ Q,
                                                  const float* __restrict__ K,
                                                  const float* __restrict__ V)
{
    const int which = blockIdx.y;
    const float* src = (which == 0) ? Q : (which == 1) ? K : V;
    __half* dh = (which == 0) ? g_QH : (which == 1) ? g_KH : g_VH;
    __half* dl = (which == 0) ? g_QL : g_KL;
    const float sc = (which == 0) ? 0.125f : 1.0f;

    size_t i = ((size_t)blockIdx.x * 256 + threadIdx.x) * 4;
    float4 f = *(const float4*)(src + i);
    f.x *= sc; f.y *= sc; f.z *= sc; f.w *= sc;
    uint2 h;
    h.x = pack_hi2(f.x, f.y); h.y = pack_hi2(f.z, f.w);
    *(uint2*)(dh + i) = h;
    if (which != 2) {
        uint2 l;
        l.x = pack_lo2(f.x, f.y); l.y = pack_lo2(f.z, f.w);
        *(uint2*)(dl + i) = l;
    }
}

// load one 64-row fp16 hi/lo K tile pair
__device__ __forceinline__ void pf_k(const __half* __restrict__ gh,
                                     const __half* __restrict__ gl,
                                     char* buf, int tid)
{
    #pragma unroll
    for (int it = 0; it < 2; ++it) {
        int idx = tid + it * NT;          // 0..511
        int r = idx >> 3, c = idx & 7;
        cp16(buf + r * KROWB + c * 16,          (const char*)(gh + r * DD_) + c * 16);
        cp16(buf + KVHALF + r * KROWB + c * 16, (const char*)(gl + r * DD_) + c * 16);
    }
}
// load one 64-row fp16 V tile (single plane)
__device__ __forceinline__ void pf_v(const __half* __restrict__ gh, char* buf, int tid)
{
    #pragma unroll
    for (int it = 0; it < 2; ++it) {
        int idx = tid + it * NT;          // 0..511
        int r = idx >> 3, c = idx & 7;
        cp16(buf + r * KROWB + c * 16, (const char*)(gh + r * DD_) + c * 16);
    }
}

// ---------------- kernel 2: fused attention (2 CTAs/SM, TQ=32) ----------------
__global__ void __launch_bounds__(NT, 2)
attn_kernel(const int* __restrict__ Mg, const float* __restrict__ QMg,
            float* __restrict__ out_o, float* __restrict__ out_a)
{
    extern __shared__ char smem[];
    char* kvb   = smem + OFF_KV;
    char* qbase = smem + OFF_Q;

    const int tid  = threadIdx.x;
    const int lane = tid & 31;
    const int wid  = tid >> 5;            // 0..7
    const int bh   = blockIdx.y;
    const int q0   = blockIdx.x * TQ_;

    const size_t qoff = ((size_t)bh * LQ_ + q0) * DD_;
    const size_t koff = (size_t)bh * LK_ * DD_;

    // ---- prefetch Q hi/lo (512 chunks, 2/thread) + K0/K1 ----
    #pragma unroll
    for (int ch = tid; ch < 512; ch += NT) {
        int pl = ch >> 8, t2 = ch & 255;
        int r = t2 >> 3, c = t2 & 7;
        const __half* src = pl ? (g_QL + qoff) : (g_QH + qoff);
        cp16(qbase + pl * QPLANE + r * KROWB + c * 16, (const char*)(src + r * DD_) + c * 16);
    }
    pf_k(g_KH + koff, g_KL + koff, kvb, tid);
    cp_commit();
    pf_k(g_KH + koff + KTROWS * DD_, g_KL + koff + KTROWS * DD_, kvb + KVBUFSZ, tid);
    cp_commit();

    // ================ phase 2: S = (Q/8)K^T -> Pbuf fp16 ================
    const int qh2 = wid >> 2, kg = wid & 3;
    const int q0w = qh2 * 16, kb0 = kg * 16;

    uint32_t aH[4][4], aL[4][4];

    #pragma unroll 1
    for (int t = 0; t < 16; ++t) {
        cp_wait1();
        __syncthreads();

        if (t == 0) {
            const uint32_t uH = s2u(qbase), uL = uH + QPLANE;
            const int arow = q0w + (lane & 15);
            #pragma unroll
            for (int ds = 0; ds < 4; ++ds) {
                const int acol = ds * 16 + ((lane >> 4) & 1) * 8;
                lm4(aH[ds], uH + arow * KROWB + acol * 2);
                lm4(aL[ds], uL + arow * KROWB + acol * 2);
            }
        }

        const uint32_t sH = s2u(kvb + (t & 1) * KVBUFSZ);
        const uint32_t sL = sH + KVHALF;

        float accA[2][4], accB[2][4];
        #pragma unroll
        for (int j = 0; j < 2; ++j)
            #pragma unroll
            for (int e = 0; e < 4; ++e) { accA[j][e] = 0.f; accB[j][e] = 0.f; }

        const int brow = kb0 + ((lane >> 4) & 1) * 8 + (lane & 7);
        #pragma unroll
        for (int ds = 0; ds < 4; ++ds) {
            const int bcol = ds * 16 + ((lane >> 3) & 1) * 8;
            uint32_t bH[4], bL[4];
            lm4(bH, sH + brow * KROWB + bcol * 2);
            lm4(bL, sL + brow * KROWB + bcol * 2);
            mma16816(accA[0], aH[ds], bH[0], bH[1]);
            mma16816(accB[0], aH[ds], bL[0], bL[1]);
            mma16816(accA[0], aL[ds], bH[0], bH[1]);
            mma16816(accA[1], aH[ds], bH[2], bH[3]);
            mma16816(accB[1], aH[ds], bL[2], bL[3]);
            mma16816(accA[1], aL[ds], bH[2], bH[3]);
        }

        // writeback raw S as fp16
        const int srow = q0w + (lane >> 2);
        char* r0 = smem + srow * PSTR_H;
        char* r1 = smem + (srow + 8) * PSTR_H;
        #pragma unroll
        for (int j = 0; j < 2; ++j) {
            const int col = t * KTROWS + kb0 + j * 8 + 2 * (lane & 3);
            *(uint32_t*)(r0 + col * 2) =
                pack_hi2(accA[j][0] + accB[j][0], accA[j][1] + accB[j][1]);
            *(uint32_t*)(r1 + col * 2) =
                pack_hi2(accA[j][2] + accB[j][2], accA[j][3] + accB[j][3]);
        }

        __syncthreads();
        if (t + 2 < 16) {
            pf_k(g_KH + koff + (size_t)(t + 2) * KTROWS * DD_,
                 g_KL + koff + (size_t)(t + 2) * KTROWS * DD_, kvb + (t & 1) * KVBUFSZ, tid);
        } else {
            // V0 -> vbuf0 (dead Q planes), V1 -> vbuf1 (K buf0 hi region)
            pf_v(g_VH + koff + (size_t)(t + 2 - 16) * KTROWS * DD_,
                 (t == 14) ? qbase : kvb, tid);
        }
        cp_commit();
    }

    // ================ phase 3: mask + softmax; p into fp16 planes (out_a deferred) ==========
    #pragma unroll 1
    for (int i = 0; i < 4; ++i) {
        const int q = wid * 4 + i;
        char* rowb = smem + q * PSTR_H;
        const int4* mrow = (const int4*)(Mg + ((size_t)bh * LQ_ + q0 + q) * LK_);

        float v[32];
        float mx = -3.0e38f;
        #pragma unroll
        for (int c = 0; c < 4; ++c) {
            const int idx = c * 32 + lane;
            uint4 sv = *(uint4*)(rowb + idx * 16);
            int4 ma = mrow[idx * 2], mb = mrow[idx * 2 + 1];
            float2 f0 = __half22float2(*(__half2*)&sv.x);
            float2 f1 = __half22float2(*(__half2*)&sv.y);
            float2 f2 = __half22float2(*(__half2*)&sv.z);
            float2 f3 = __half22float2(*(__half2*)&sv.w);
            float* vv = v + c * 8;
            vv[0] = (ma.x == 0) ? -1.0e9f : f0.x;
            vv[1] = (ma.y == 0) ? -1.0e9f : f0.y;
            vv[2] = (ma.z == 0) ? -1.0e9f : f1.x;
            vv[3] = (ma.w == 0) ? -1.0e9f : f1.y;
            vv[4] = (mb.x == 0) ? -1.0e9f : f2.x;
            vv[5] = (mb.y == 0) ? -1.0e9f : f2.y;
            vv[6] = (mb.z == 0) ? -1.0e9f : f3.x;
            vv[7] = (mb.w == 0) ? -1.0e9f : f3.y;
            #pragma unroll
            for (int e = 0; e < 8; ++e) mx = fmaxf(mx, vv[e]);
        }
        #pragma unroll
        for (int o = 16; o > 0; o >>= 1)
            mx = fmaxf(mx, __shfl_xor_sync(0xffffffffu, mx, o));

        float sum = 0.f;
        #pragma unroll
        for (int e = 0; e < 32; ++e) { v[e] = __expf(v[e] - mx); sum += v[e]; }
        #pragma unroll
        for (int o = 16; o > 0; o >>= 1)
            sum += __shfl_xor_sync(0xffffffffu, sum, o);

        const float sc = QMg[(size_t)bh * LQ_ + q0 + q] / sum;
        #pragma unroll
        for (int c = 0; c < 4; ++c) {
            const int idx = c * 32 + lane;
            float* vv = v + c * 8;
            #pragma unroll
            for (int e = 0; e < 8; ++e) vv[e] *= sc;
            uint4 pk;
            pk.x = pack_hi2(vv[0], vv[1]); pk.y = pack_hi2(vv[2], vv[3]);
            pk.z = pack_hi2(vv[4], vv[5]); pk.w = pack_hi2(vv[6], vv[7]);
            *(uint4*)(rowb + idx * 16) = pk;
        }
    }

    // ================ phase 4: O = P @ V + streamed out_a (V triple-buffered) ================
    const int qh4 = wid >> 2, nblk = wid & 3;
    const int q0o = qh4 * 16, n0 = nblk * 16;
    const uint32_t pbase = s2u(smem);

    char* vt0 = qbase;            // V(t)
    char* vt1 = kvb;              // V(t+1)
    char* vt2 = kvb + KVHALF;     // prefetch target V(t+2)

    float oa[2][4];
    #pragma unroll
    for (int j = 0; j < 2; ++j)
        #pragma unroll
        for (int e = 0; e < 4; ++e) oa[j][e] = 0.f;

    const int arow = q0o + (lane & 15);
    const int vrl  = ((lane >> 3) & 1) * 8 + (lane & 7);
    const int vcol = n0 + ((lane >> 4) & 1) * 8;

    // out_a streaming map: thread -> (row sr_, cols c8_..c8_+7) of each 32x64 tile
    const int sr_ = tid >> 3;
    const int c8_ = (tid & 7) * 8;
    float* abase = out_a ? (out_a + ((size_t)bh * LQ_ + q0 + sr_) * LK_ + c8_) : nullptr;
    const char* srcrow = smem + sr_ * PSTR_H + c8_ * 2;

    #pragma unroll 1
    for (int t = 0; t < 16; ++t) {
        cp_wait1();
        __syncthreads();                 // t==0 also publishes phase-3 p planes

        const uint32_t vH = s2u(vt0);

        // stream out_a for this tile from the p planes (overlaps with MMA issue below)
        if (abase) {
            uint4 pk = *(const uint4*)(srcrow + t * (KTROWS * 2));
            float2 f0 = __half22float2(*(__half2*)&pk.x);
            float2 f1 = __half22float2(*(__half2*)&pk.y);
            float2 f2 = __half22float2(*(__half2*)&pk.z);
            float2 f3 = __half22float2(*(__half2*)&pk.w);
            __stcs((float4*)(abase + t * KTROWS),     make_float4(f0.x, f0.y, f1.x, f1.y));
            __stcs((float4*)(abase + t * KTROWS + 4), make_float4(f2.x, f2.y, f3.x, f3.y));
        }

        #pragma unroll
        for (int ks = 0; ks < 4; ++ks) {
            const int k0 = ks * 16;
            uint32_t a4[4];
            const uint32_t ab = pbase + arow * PSTR_H +
                                2 * (t * KTROWS + k0 + ((lane >> 4) & 1) * 8);
            lm4(a4, ab);

            uint32_t b4[4];
            const uint32_t vb = (uint32_t)(k0 + vrl) * KROWB + vcol * 2;
            lm4t(b4, vH + vb);

            mma16816(oa[0], a4, b4[0], b4[1]);
            mma16816(oa[1], a4, b4[2], b4[3]);
        }

        if (t + 2 < 16)
            pf_v(g_VH + koff + (size_t)(t + 2) * KTROWS * DD_, vt2, tid);
        cp_commit();                     // commit every iter (keeps group counting exact)

        char* tmp = vt0; vt0 = vt1; vt1 = vt2; vt2 = tmp;
    }

    if (out_o) {
        const int row0 = q0 + q0o + (lane >> 2);
        #pragma unroll
        for (int j = 0; j < 2; ++j) {
            const int cl = j * 8 + 2 * (lane & 3);
            float* o0 = out_o + ((size_t)bh * LQ_ + row0) * DD_ + n0 + cl;
            *(float2*)o0 = make_float2(oa[j][0], oa[j][1]);
            *(float2*)(o0 + 8 * DD_) = make_float2(oa[j][2], oa[j][3]);
        }
    }
}

extern "C" void kernel_launch(void* const* d_in, const int* in_sizes, int n_in,
                              void* d_out, int out_size)
{
    const float* q  = (const float*)d_in[0];
    const float* k  = (const float*)d_in[1];
    const float* v  = (const float*)d_in[2];
    const int*   m  = (const int*)d_in[3];
    const float* qm = (const float*)d_in[4];

    const long long NO = (long long)BH_ * LQ_ * DD_;
    const long long NA = (long long)BH_ * LQ_ * LK_;

    float* out_o = nullptr;
    float* out_a = nullptr;
    if ((long long)out_size >= NO + NA) {
        out_o = (float*)d_out;
        out_a = (float*)d_out + NO;
    } else if ((long long)out_size == NA) {
        out_a = (float*)d_out;
    } else {
        out_o = (float*)d_out;
    }

    cvt_kernel<<<dim3((BH_*LQ_*DD_) / (256 * 4), 3), 256>>>(q, k, v);

    cudaFuncSetAttribute(attn_kernel,
                         cudaFuncAttributeMaxDynamicSharedMemorySize, SM_TOTAL);
    attn_kernel<<<dim3(LQ_ / TQ_, BH_), NT, SM_TOTAL>>>(m, qm, out_o, out_a);
}

// round 13
// speedup vs baseline: 1.0611x; 1.0611x over previous
#include <cuda_runtime.h>
#include <cuda_fp16.h>
#include <cstdint>

#define BH_  64
#define LQ_  1024
#define LK_  1024
#define DD_  64
#define TQ_  32
#define NT   256
#define PSTR_H 2064          // S/P row bytes (1032 fp16; 129×16B -> conflict-free ldmatrix)
#define KROWB  144           // K/V smem row bytes (72 fp16)
#define KTROWS 64            // K/V tile rows
#define OFF_KV (TQ_*PSTR_H)            // 66048
#define KVHALF (KTROWS*KROWB)          // 9216
#define KVBUFSZ (2*KVHALF)             // 18432 (K: hi+lo; V: hi in first half)
#define OFF_Q  (OFF_KV + 2*KVBUFSZ)    // 102912
#define QPLANE (TQ_*KROWB)             // 4608 (Q hi only now)
#define SM_TOTAL (OFF_Q + 2*QPLANE)    // 112128 -> 2 CTAs/SM

__device__ __half g_QH[BH_*LQ_*DD_];
__device__ __half g_KH[BH_*LK_*DD_];
__device__ __half g_KL[BH_*LK_*DD_];
__device__ __half g_VH[BH_*LK_*DD_];

__device__ __forceinline__ uint32_t s2u(const void* p) {
    uint32_t a;
    asm("{.reg .u64 t; cvta.to.shared.u64 t, %1; cvt.u32.u64 %0, t;}" : "=r"(a) : "l"(p));
    return a;
}
__device__ __forceinline__ void lm4(uint32_t* r, uint32_t addr) {
    asm volatile("ldmatrix.sync.aligned.m8n8.x4.shared.b16 {%0,%1,%2,%3}, [%4];"
                 : "=r"(r[0]), "=r"(r[1]), "=r"(r[2]), "=r"(r[3]) : "r"(addr));
}
__device__ __forceinline__ void lm4t(uint32_t* r, uint32_t addr) {
    asm volatile("ldmatrix.sync.aligned.m8n8.x4.trans.shared.b16 {%0,%1,%2,%3}, [%4];"
                 : "=r"(r[0]), "=r"(r[1]), "=r"(r[2]), "=r"(r[3]) : "r"(addr));
}
__device__ __forceinline__ void mma16816(float* c, const uint32_t* a, uint32_t b0, uint32_t b1) {
    asm volatile("mma.sync.aligned.m16n8k16.row.col.f32.f16.f16.f32 "
                 "{%0,%1,%2,%3}, {%4,%5,%6,%7}, {%8,%9}, {%0,%1,%2,%3};"
                 : "+f"(c[0]), "+f"(c[1]), "+f"(c[2]), "+f"(c[3])
                 : "r"(a[0]), "r"(a[1]), "r"(a[2]), "r"(a[3]), "r"(b0), "r"(b1));
}
__device__ __forceinline__ void cp16(char* dst, const void* src) {
    uint32_t s = s2u(dst);
    asm volatile("cp.async.cg.shared.global [%0], [%1], 16;" :: "r"(s), "l"(src));
}
__device__ __forceinline__ void cp_commit() { asm volatile("cp.async.commit_group;"); }
__device__ __forceinline__ void cp_wait0() { asm volatile("cp.async.wait_group 0;"); }
__device__ __forceinline__ void cp_wait1() { asm volatile("cp.async.wait_group 1;"); }

__device__ __forceinline__ uint32_t pack_hi2(float a, float b) {
    __half2 h = __floats2half2_rn(a, b);
    return *(uint32_t*)&h;
}
__device__ __forceinline__ uint32_t pack_lo2(float a, float b) {
    float ra = a - __half2float(__float2half_rn(a));
    float rb = b - __half2float(__float2half_rn(b));
    __half2 l = __floats2half2_rn(ra, rb);
    return *(uint32_t*)&l;
}

// ---------------- kernel 1: fp32 -> fp16 splits (Q hi; K hi+lo; V hi) ----------------
__global__ void __launch_bounds__(256) cvt_kernel(const float* __restrict__ Q,
                                                  const float* __restrict__ K,
                                                  const float* __restrict__ V)
{
    const int which = blockIdx.y;
    const float* src = (which == 0) ? Q : (which == 1) ? K : V;
    __half* dh = (which == 0) ? g_QH : (which == 1) ? g_KH : g_VH;
    const float sc = (which == 0) ? 0.125f : 1.0f;

    size_t i = ((size_t)blockIdx.x * 256 + threadIdx.x) * 4;
    float4 f = *(const float4*)(src + i);
    f.x *= sc; f.y *= sc; f.z *= sc; f.w *= sc;
    uint2 h;
    h.x = pack_hi2(f.x, f.y); h.y = pack_hi2(f.z, f.w);
    *(uint2*)(dh + i) = h;
    if (which == 1) {
        uint2 l;
        l.x = pack_lo2(f.x, f.y); l.y = pack_lo2(f.z, f.w);
        *(uint2*)(g_KL + i) = l;
    }
}

// load one 64-row fp16 hi/lo K tile pair
__device__ __forceinline__ void pf_k(const __half* __restrict__ gh,
                                     const __half* __restrict__ gl,
                                     char* buf, int tid)
{
    #pragma unroll
    for (int it = 0; it < 2; ++it) {
        int idx = tid + it * NT;          // 0..511
        int r = idx >> 3, c = idx & 7;
        cp16(buf + r * KROWB + c * 16,          (const char*)(gh + r * DD_) + c * 16);
        cp16(buf + KVHALF + r * KROWB + c * 16, (const char*)(gl + r * DD_) + c * 16);
    }
}
// load one 64-row fp16 V tile (single plane)
__device__ __forceinline__ void pf_v(const __half* __restrict__ gh, char* buf, int tid)
{
    #pragma unroll
    for (int it = 0; it < 2; ++it) {
        int idx = tid + it * NT;          // 0..511
        int r = idx >> 3, c = idx & 7;
        cp16(buf + r * KROWB + c * 16, (const char*)(gh + r * DD_) + c * 16);
    }
}

// ---------------- kernel 2: fused attention (2 CTAs/SM, TQ=32) ----------------
__global__ void __launch_bounds__(NT, 2)
attn_kernel(const int* __restrict__ Mg, const float* __restrict__ QMg,
            float* __restrict__ out_o, float* __restrict__ out_a)
{
    extern __shared__ char smem[];
    char* kvb   = smem + OFF_KV;
    char* qbase = smem + OFF_Q;

    const int tid  = threadIdx.x;
    const int lane = tid & 31;
    const int wid  = tid >> 5;            // 0..7
    const int bh   = blockIdx.y;
    const int q0   = blockIdx.x * TQ_;

    const size_t qoff = ((size_t)bh * LQ_ + q0) * DD_;
    const size_t koff = (size_t)bh * LK_ * DD_;

    // ---- prefetch Q hi (256 chunks, 1/thread) + K0/K1 ----
    {
        int r = tid >> 3, c = tid & 7;
        cp16(qbase + r * KROWB + c * 16, (const char*)(g_QH + qoff + r * DD_) + c * 16);
    }
    pf_k(g_KH + koff, g_KL + koff, kvb, tid);
    cp_commit();
    pf_k(g_KH + koff + KTROWS * DD_, g_KL + koff + KTROWS * DD_, kvb + KVBUFSZ, tid);
    cp_commit();

    // ================ phase 2: S = (Q/8)K^T -> Pbuf fp16 (Q hi-plane only) ================
    const int qh2 = wid >> 2, kg = wid & 3;
    const int q0w = qh2 * 16, kb0 = kg * 16;

    uint32_t aH[4][4];

    #pragma unroll 1
    for (int t = 0; t < 16; ++t) {
        cp_wait1();
        __syncthreads();

        if (t == 0) {
            const uint32_t uH = s2u(qbase);
            const int arow = q0w + (lane & 15);
            #pragma unroll
            for (int ds = 0; ds < 4; ++ds) {
                const int acol = ds * 16 + ((lane >> 4) & 1) * 8;
                lm4(aH[ds], uH + arow * KROWB + acol * 2);
            }
        }

        const uint32_t sH = s2u(kvb + (t & 1) * KVBUFSZ);
        const uint32_t sL = sH + KVHALF;

        float accA[2][4], accB[2][4];
        #pragma unroll
        for (int j = 0; j < 2; ++j)
            #pragma unroll
            for (int e = 0; e < 4; ++e) { accA[j][e] = 0.f; accB[j][e] = 0.f; }

        const int brow = kb0 + ((lane >> 4) & 1) * 8 + (lane & 7);
        #pragma unroll
        for (int ds = 0; ds < 4; ++ds) {
            const int bcol = ds * 16 + ((lane >> 3) & 1) * 8;
            uint32_t bH[4], bL[4];
            lm4(bH, sH + brow * KROWB + bcol * 2);
            lm4(bL, sL + brow * KROWB + bcol * 2);
            mma16816(accA[0], aH[ds], bH[0], bH[1]);
            mma16816(accB[0], aH[ds], bL[0], bL[1]);
            mma16816(accA[1], aH[ds], bH[2], bH[3]);
            mma16816(accB[1], aH[ds], bL[2], bL[3]);
        }

        // writeback raw S as fp16
        const int srow = q0w + (lane >> 2);
        char* r0 = smem + srow * PSTR_H;
        char* r1 = smem + (srow + 8) * PSTR_H;
        #pragma unroll
        for (int j = 0; j < 2; ++j) {
            const int col = t * KTROWS + kb0 + j * 8 + 2 * (lane & 3);
            *(uint32_t*)(r0 + col * 2) =
                pack_hi2(accA[j][0] + accB[j][0], accA[j][1] + accB[j][1]);
            *(uint32_t*)(r1 + col * 2) =
                pack_hi2(accA[j][2] + accB[j][2], accA[j][3] + accB[j][3]);
        }

        __syncthreads();
        if (t + 2 < 16) {
            pf_k(g_KH + koff + (size_t)(t + 2) * KTROWS * DD_,
                 g_KL + koff + (size_t)(t + 2) * KTROWS * DD_, kvb + (t & 1) * KVBUFSZ, tid);
        } else {
            pf_v(g_VH + koff + (size_t)(t + 2 - 16) * KTROWS * DD_,
                 kvb + (t & 1) * KVBUFSZ, tid);
        }
        cp_commit();
    }

    // ================ phase 3: mask + softmax; p back as fp16 + out_a fp32 ================
    #pragma unroll 1
    for (int i = 0; i < 4; ++i) {
        const int q = wid * 4 + i;
        char* rowb = smem + q * PSTR_H;
        const int4* mrow = (const int4*)(Mg + ((size_t)bh * LQ_ + q0 + q) * LK_);

        float v[32];
        float mx = -3.0e38f;
        #pragma unroll
        for (int c = 0; c < 4; ++c) {
            const int idx = c * 32 + lane;
            uint4 sv = *(uint4*)(rowb + idx * 16);
            int4 ma = mrow[idx * 2], mb = mrow[idx * 2 + 1];
            float2 f0 = __half22float2(*(__half2*)&sv.x);
            float2 f1 = __half22float2(*(__half2*)&sv.y);
            float2 f2 = __half22float2(*(__half2*)&sv.z);
            float2 f3 = __half22float2(*(__half2*)&sv.w);
            float* vv = v + c * 8;
            vv[0] = (ma.x == 0) ? -1.0e9f : f0.x;
            vv[1] = (ma.y == 0) ? -1.0e9f : f0.y;
            vv[2] = (ma.z == 0) ? -1.0e9f : f1.x;
            vv[3] = (ma.w == 0) ? -1.0e9f : f1.y;
            vv[4] = (mb.x == 0) ? -1.0e9f : f2.x;
            vv[5] = (mb.y == 0) ? -1.0e9f : f2.y;
            vv[6] = (mb.z == 0) ? -1.0e9f : f3.x;
            vv[7] = (mb.w == 0) ? -1.0e9f : f3.y;
            #pragma unroll
            for (int e = 0; e < 8; ++e) mx = fmaxf(mx, vv[e]);
        }
        #pragma unroll
        for (int o = 16; o > 0; o >>= 1)
            mx = fmaxf(mx, __shfl_xor_sync(0xffffffffu, mx, o));

        float sum = 0.f;
        #pragma unroll
        for (int e = 0; e < 32; ++e) { v[e] = __expf(v[e] - mx); sum += v[e]; }
        #pragma unroll
        for (int o = 16; o > 0; o >>= 1)
            sum += __shfl_xor_sync(0xffffffffu, sum, o);

        const float sc = QMg[(size_t)bh * LQ_ + q0 + q] / sum;
        float* arow = out_a ? (out_a + ((size_t)bh * LQ_ + q0 + q) * LK_) : nullptr;
        #pragma unroll
        for (int c = 0; c < 4; ++c) {
            const int idx = c * 32 + lane;
            float* vv = v + c * 8;
            #pragma unroll
            for (int e = 0; e < 8; ++e) vv[e] *= sc;
            if (arow) {
                __stcs((float4*)(arow + idx * 8),     make_float4(vv[0], vv[1], vv[2], vv[3]));
                __stcs((float4*)(arow + idx * 8 + 4), make_float4(vv[4], vv[5], vv[6], vv[7]));
            }
            uint4 pk;
            pk.x = pack_hi2(vv[0], vv[1]); pk.y = pack_hi2(vv[2], vv[3]);
            pk.z = pack_hi2(vv[4], vv[5]); pk.w = pack_hi2(vv[6], vv[7]);
            *(uint4*)(rowb + idx * 16) = pk;
        }
    }

    // ================ phase 4: O = P @ V — warp = (qh4, nh n32, kh k-split) ================
    const int qh4 = wid >> 2;            // 0..1
    const int nh  = (wid >> 1) & 1;      // 0..1
    const int kh  = wid & 1;             // 0..1
    const int q0o = qh4 * 16, n0 = nh * 32;
    const uint32_t pbase = s2u(smem);

    float oa[4][4];
    #pragma unroll
    for (int j = 0; j < 4; ++j)
        #pragma unroll
        for (int e = 0; e < 4; ++e) oa[j][e] = 0.f;

    const int arow = q0o + (lane & 15);
    const int vrl  = ((lane >> 3) & 1) * 8 + (lane & 7);
    const int vsub = ((lane >> 4) & 1) * 8;

    #pragma unroll 1
    for (int t = 0; t < 16; ++t) {
        if (t == 15) cp_wait0(); else cp_wait1();
        __syncthreads();                 // t==0 also publishes phase-3 p planes

        const uint32_t vH = s2u(kvb + (t & 1) * KVBUFSZ);

        #pragma unroll
        for (int ks = 0; ks < 2; ++ks) {
            const int k0 = kh * 32 + ks * 16;
            uint32_t a4[4];
            const uint32_t ab = pbase + arow * PSTR_H +
                                2 * (t * KTROWS + k0 + ((lane >> 4) & 1) * 8);
            lm4(a4, ab);

            const uint32_t vrow = (uint32_t)(k0 + vrl) * KROWB;
            #pragma unroll
            for (int nb2 = 0; nb2 < 2; ++nb2) {
                uint32_t b4[4];
                lm4t(b4, vH + vrow + (uint32_t)(n0 + nb2 * 16 + vsub) * 2);
                mma16816(oa[nb2 * 2 + 0], a4, b4[0], b4[1]);
                mma16816(oa[nb2 * 2 + 1], a4, b4[2], b4[3]);
            }
        }

        __syncthreads();
        if (t + 2 < 16) {
            pf_v(g_VH + koff + (size_t)(t + 2) * KTROWS * DD_,
                 kvb + (t & 1) * KVBUFSZ, tid);
            cp_commit();
        }
    }

    // ---- kh reduction via scratch in dead K-lo region ----
    float* scr = (float*)(kvb + KVHALF);   // [4 grp][16][34] floats = 8704 B
    const int grp = qh4 * 2 + nh;
    __syncthreads();
    if (kh == 1) {
        #pragma unroll
        for (int j = 0; j < 4; ++j) {
            const int cl = j * 8 + 2 * (lane & 3);
            float* s0 = scr + grp * (16 * 34) + (lane >> 2) * 34 + cl;
            *(float2*)s0 = make_float2(oa[j][0], oa[j][1]);
            *(float2*)(s0 + 8 * 34) = make_float2(oa[j][2], oa[j][3]);
        }
    }
    __syncthreads();
    if (kh == 0 && out_o) {
        const int row0 = q0 + q0o + (lane >> 2);
        #pragma unroll
        for (int j = 0; j < 4; ++j) {
            const int cl = j * 8 + 2 * (lane & 3);
            float2 s0 = *(float2*)(scr + grp * (16 * 34) + (lane >> 2) * 34 + cl);
            float2 s1 = *(float2*)(scr + grp * (16 * 34) + ((lane >> 2) + 8) * 34 + cl);
            float* o0 = out_o + ((size_t)bh * LQ_ + row0) * DD_ + n0 + cl;
            *(float2*)o0 = make_float2(oa[j][0] + s0.x, oa[j][1] + s0.y);
            *(float2*)(o0 + 8 * DD_) = make_float2(oa[j][2] + s1.x, oa[j][3] + s1.y);
        }
    }
}

extern "C" void kernel_launch(void* const* d_in, const int* in_sizes, int n_in,
                              void* d_out, int out_size)
{
    const float* q  = (const float*)d_in[0];
    const float* k  = (const float*)d_in[1];
    const float* v  = (const float*)d_in[2];
    const int*   m  = (const int*)d_in[3];
    const float* qm = (const float*)d_in[4];

    const long long NO = (long long)BH_ * LQ_ * DD_;
    const long long NA = (long long)BH_ * LQ_ * LK_;

    float* out_o = nullptr;
    float* out_a = nullptr;
    if ((long long)out_size >= NO + NA) {
        out_o = (float*)d_out;
        out_a = (float*)d_out + NO;
    } else if ((long long)out_size == NA) {
        out_a = (float*)d_out;
    } else {
        out_o = (float*)d_out;
    }

    cvt_kernel<<<dim3((BH_*LQ_*DD_) / (256 * 4), 3), 256>>>(q, k, v);

    cudaFuncSetAttribute(attn_kernel,
                         cudaFuncAttributeMaxDynamicSharedMemorySize, SM_TOTAL);
    attn_kernel<<<dim3(LQ_ / TQ_, BH_), NT, SM_TOTAL>>>(m, qm, out_o, out_a);
}

// round 14
// speedup vs baseline: 1.2494x; 1.1774x over previous
#include <cuda_runtime.h>
#include <cuda_fp16.h>
#include <cstdint>

#define BH_  64
#define LQ_  1024
#define LK_  1024
#define DD_  64
#define TQ_  32
#define NT   256
#define PSTR_H 2064          // S/P row bytes (1032 fp16; 129×16B -> conflict-free ldmatrix)
#define KROWB  144           // K/V smem row bytes (72 fp16)
#define KTILE  128           // K tile rows (single plane)
#define VTROWS 64            // V tile rows
#define OFF_KV (TQ_*PSTR_H)            // 66048
#define KBUFSZ (KTILE*KROWB)           // 18432 (one 128-row K tile)
#define VHALF  (VTROWS*KROWB)          // 9216  (one 64-row V tile)
#define OFF_Q  (OFF_KV + 2*KBUFSZ)     // 102912
#define QPLANE (TQ_*KROWB)             // 4608
#define SM_TOTAL (OFF_Q + QPLANE)      // 107520 -> 2 CTAs/SM

__device__ __half g_QH[BH_*LQ_*DD_];
__device__ __half g_KH[BH_*LK_*DD_];
__device__ __half g_VH[BH_*LK_*DD_];

__device__ __forceinline__ uint32_t s2u(const void* p) {
    uint32_t a;
    asm("{.reg .u64 t; cvta.to.shared.u64 t, %1; cvt.u32.u64 %0, t;}" : "=r"(a) : "l"(p));
    return a;
}
__device__ __forceinline__ void lm4(uint32_t* r, uint32_t addr) {
    asm volatile("ldmatrix.sync.aligned.m8n8.x4.shared.b16 {%0,%1,%2,%3}, [%4];"
                 : "=r"(r[0]), "=r"(r[1]), "=r"(r[2]), "=r"(r[3]) : "r"(addr));
}
__device__ __forceinline__ void lm4t(uint32_t* r, uint32_t addr) {
    asm volatile("ldmatrix.sync.aligned.m8n8.x4.trans.shared.b16 {%0,%1,%2,%3}, [%4];"
                 : "=r"(r[0]), "=r"(r[1]), "=r"(r[2]), "=r"(r[3]) : "r"(addr));
}
__device__ __forceinline__ void mma16816(float* c, const uint32_t* a, uint32_t b0, uint32_t b1) {
    asm volatile("mma.sync.aligned.m16n8k16.row.col.f32.f16.f16.f32 "
                 "{%0,%1,%2,%3}, {%4,%5,%6,%7}, {%8,%9}, {%0,%1,%2,%3};"
                 : "+f"(c[0]), "+f"(c[1]), "+f"(c[2]), "+f"(c[3])
                 : "r"(a[0]), "r"(a[1]), "r"(a[2]), "r"(a[3]), "r"(b0), "r"(b1));
}
__device__ __forceinline__ void cp16(char* dst, const void* src) {
    uint32_t s = s2u(dst);
    asm volatile("cp.async.cg.shared.global [%0], [%1], 16;" :: "r"(s), "l"(src));
}
__device__ __forceinline__ void cp_commit() { asm volatile("cp.async.commit_group;"); }
__device__ __forceinline__ void cp_wait0() { asm volatile("cp.async.wait_group 0;"); }
__device__ __forceinline__ void cp_wait1() { asm volatile("cp.async.wait_group 1;"); }

__device__ __forceinline__ uint32_t pack_hi2(float a, float b) {
    __half2 h = __floats2half2_rn(a, b);
    return *(uint32_t*)&h;
}

// ---------------- kernel 1: fp32 -> fp16 (single plane each) ----------------
__global__ void __launch_bounds__(256) cvt_kernel(const float* __restrict__ Q,
                                                  const float* __restrict__ K,
                                                  const float* __restrict__ V)
{
    const int which = blockIdx.y;
    const float* src = (which == 0) ? Q : (which == 1) ? K : V;
    __half* dh = (which == 0) ? g_QH : (which == 1) ? g_KH : g_VH;
    const float sc = (which == 0) ? 0.125f : 1.0f;

    size_t i = ((size_t)blockIdx.x * 256 + threadIdx.x) * 4;
    float4 f = *(const float4*)(src + i);
    f.x *= sc; f.y *= sc; f.z *= sc; f.w *= sc;
    uint2 h;
    h.x = pack_hi2(f.x, f.y); h.y = pack_hi2(f.z, f.w);
    *(uint2*)(dh + i) = h;
}

// load one 128-row fp16 K tile (single plane)
__device__ __forceinline__ void pf_k128(const __half* __restrict__ gh, char* buf, int tid) {
    #pragma unroll
    for (int it = 0; it < 4; ++it) {
        int idx = tid + it * NT;          // 0..1023
        int r = idx >> 3, c = idx & 7;
        cp16(buf + r * KROWB + c * 16, (const char*)(gh + r * DD_) + c * 16);
    }
}
// load one 64-row fp16 V tile (single plane)
__device__ __forceinline__ void pf_v(const __half* __restrict__ gh, char* buf, int tid) {
    #pragma unroll
    for (int it = 0; it < 2; ++it) {
        int idx = tid + it * NT;          // 0..511
        int r = idx >> 3, c = idx & 7;
        cp16(buf + r * KROWB + c * 16, (const char*)(gh + r * DD_) + c * 16);
    }
}

// ---------------- kernel 2: fused attention (2 CTAs/SM, TQ=32) ----------------
__global__ void __launch_bounds__(NT, 2)
attn_kernel(const int* __restrict__ Mg, const float* __restrict__ QMg,
            float* __restrict__ out_o, float* __restrict__ out_a)
{
    extern __shared__ char smem[];
    char* kvb   = smem + OFF_KV;
    char* qbase = smem + OFF_Q;

    const int tid  = threadIdx.x;
    const int lane = tid & 31;
    const int wid  = tid >> 5;            // 0..7
    const int bh   = blockIdx.y;
    const int q0   = blockIdx.x * TQ_;

    const size_t qoff = ((size_t)bh * LQ_ + q0) * DD_;
    const size_t koff = (size_t)bh * LK_ * DD_;

    // ---- prefetch Q (1 chunk/thread) + K tiles 0/1 ----
    {
        int r = tid >> 3, c = tid & 7;
        cp16(qbase + r * KROWB + c * 16, (const char*)(g_QH + qoff + r * DD_) + c * 16);
    }
    pf_k128(g_KH + koff, kvb, tid);
    cp_commit();
    pf_k128(g_KH + koff + KTILE * DD_, kvb + KBUFSZ, tid);
    cp_commit();

    // ================ phase 2: S = (Q/8)K^T -> Pbuf fp16 (8 tiles of 128 k) ================
    const int qh2 = wid >> 2, kg = wid & 3;
    const int q0w = qh2 * 16, kb0 = kg * 16;

    uint32_t aH[4][4];

    #pragma unroll 1
    for (int t = 0; t < 8; ++t) {
        cp_wait1();
        __syncthreads();

        if (t == 0) {
            const uint32_t uH = s2u(qbase);
            const int arow = q0w + (lane & 15);
            #pragma unroll
            for (int ds = 0; ds < 4; ++ds) {
                const int acol = ds * 16 + ((lane >> 4) & 1) * 8;
                lm4(aH[ds], uH + arow * KROWB + acol * 2);
            }
        }

        const uint32_t sH = s2u(kvb + (t & 1) * KBUFSZ);
        const int srow = q0w + (lane >> 2);
        char* r0 = smem + srow * PSTR_H;
        char* r1 = smem + (srow + 8) * PSTR_H;

        #pragma unroll
        for (int h = 0; h < 2; ++h) {
            float accA[2][4];
            #pragma unroll
            for (int j = 0; j < 2; ++j)
                #pragma unroll
                for (int e = 0; e < 4; ++e) accA[j][e] = 0.f;

            const int brow = h * 64 + kb0 + ((lane >> 4) & 1) * 8 + (lane & 7);
            #pragma unroll
            for (int ds = 0; ds < 4; ++ds) {
                const int bcol = ds * 16 + ((lane >> 3) & 1) * 8;
                uint32_t bH[4];
                lm4(bH, sH + brow * KROWB + bcol * 2);
                mma16816(accA[0], aH[ds], bH[0], bH[1]);
                mma16816(accA[1], aH[ds], bH[2], bH[3]);
            }

            #pragma unroll
            for (int j = 0; j < 2; ++j) {
                const int col = t * KTILE + h * 64 + kb0 + j * 8 + 2 * (lane & 3);
                *(uint32_t*)(r0 + col * 2) = pack_hi2(accA[j][0], accA[j][1]);
                *(uint32_t*)(r1 + col * 2) = pack_hi2(accA[j][2], accA[j][3]);
            }
        }

        __syncthreads();
        if (t + 2 < 8) {
            pf_k128(g_KH + koff + (size_t)(t + 2) * KTILE * DD_, kvb + (t & 1) * KBUFSZ, tid);
        } else {
            // V0 -> kvb (t=6), V1 -> kvb+KBUFSZ (t=7)
            pf_v(g_VH + koff + (size_t)(t - 6) * VTROWS * DD_, kvb + (t & 1) * KBUFSZ, tid);
        }
        cp_commit();
    }

    // ================ phase 3: mask + softmax; p back as fp16 + out_a fp32 ================
    #pragma unroll 1
    for (int i = 0; i < 4; ++i) {
        const int q = wid * 4 + i;
        char* rowb = smem + q * PSTR_H;
        const int4* mrow = (const int4*)(Mg + ((size_t)bh * LQ_ + q0 + q) * LK_);

        float v[32];
        float mx = -3.0e38f;
        #pragma unroll
        for (int c = 0; c < 4; ++c) {
            const int idx = c * 32 + lane;
            uint4 sv = *(uint4*)(rowb + idx * 16);
            int4 ma = mrow[idx * 2], mb = mrow[idx * 2 + 1];
            float2 f0 = __half22float2(*(__half2*)&sv.x);
            float2 f1 = __half22float2(*(__half2*)&sv.y);
            float2 f2 = __half22float2(*(__half2*)&sv.z);
            float2 f3 = __half22float2(*(__half2*)&sv.w);
            float* vv = v + c * 8;
            vv[0] = (ma.x == 0) ? -1.0e9f : f0.x;
            vv[1] = (ma.y == 0) ? -1.0e9f : f0.y;
            vv[2] = (ma.z == 0) ? -1.0e9f : f1.x;
            vv[3] = (ma.w == 0) ? -1.0e9f : f1.y;
            vv[4] = (mb.x == 0) ? -1.0e9f : f2.x;
            vv[5] = (mb.y == 0) ? -1.0e9f : f2.y;
            vv[6] = (mb.z == 0) ? -1.0e9f : f3.x;
            vv[7] = (mb.w == 0) ? -1.0e9f : f3.y;
            #pragma unroll
            for (int e = 0; e < 8; ++e) mx = fmaxf(mx, vv[e]);
        }
        #pragma unroll
        for (int o = 16; o > 0; o >>= 1)
            mx = fmaxf(mx, __shfl_xor_sync(0xffffffffu, mx, o));

        float sum = 0.f;
        #pragma unroll
        for (int e = 0; e < 32; ++e) { v[e] = __expf(v[e] - mx); sum += v[e]; }
        #pragma unroll
        for (int o = 16; o > 0; o >>= 1)
            sum += __shfl_xor_sync(0xffffffffu, sum, o);

        const float sc = QMg[(size_t)bh * LQ_ + q0 + q] / sum;
        float* arow = out_a ? (out_a + ((size_t)bh * LQ_ + q0 + q) * LK_) : nullptr;
        #pragma unroll
        for (int c = 0; c < 4; ++c) {
            const int idx = c * 32 + lane;
            float* vv = v + c * 8;
            #pragma unroll
            for (int e = 0; e < 8; ++e) vv[e] *= sc;
            if (arow) {
                __stcs((float4*)(arow + idx * 8),     make_float4(vv[0], vv[1], vv[2], vv[3]));
                __stcs((float4*)(arow + idx * 8 + 4), make_float4(vv[4], vv[5], vv[6], vv[7]));
            }
            uint4 pk;
            pk.x = pack_hi2(vv[0], vv[1]); pk.y = pack_hi2(vv[2], vv[3]);
            pk.z = pack_hi2(vv[4], vv[5]); pk.w = pack_hi2(vv[6], vv[7]);
            *(uint4*)(rowb + idx * 16) = pk;
        }
    }

    // ================ phase 4: O = P @ V — warp = (qh4, nh n32, kh k-split) ================
    const int qh4 = wid >> 2;            // 0..1
    const int nh  = (wid >> 1) & 1;      // 0..1
    const int kh  = wid & 1;             // 0..1
    const int q0o = qh4 * 16, n0 = nh * 32;
    const uint32_t pbase = s2u(smem);

    float oa[4][4];
    #pragma unroll
    for (int j = 0; j < 4; ++j)
        #pragma unroll
        for (int e = 0; e < 4; ++e) oa[j][e] = 0.f;

    const int arow = q0o + (lane & 15);
    const int vrl  = ((lane >> 3) & 1) * 8 + (lane & 7);
    const int vsub = ((lane >> 4) & 1) * 8;

    #pragma unroll 1
    for (int t = 0; t < 16; ++t) {
        if (t == 15) cp_wait0(); else cp_wait1();
        __syncthreads();                 // t==0 also publishes phase-3 p planes

        const uint32_t vH = s2u(kvb + (t & 1) * KBUFSZ);

        #pragma unroll
        for (int ks = 0; ks < 2; ++ks) {
            const int k0 = kh * 32 + ks * 16;
            uint32_t a4[4];
            const uint32_t ab = pbase + arow * PSTR_H +
                                2 * (t * VTROWS + k0 + ((lane >> 4) & 1) * 8);
            lm4(a4, ab);

            const uint32_t vrow = (uint32_t)(k0 + vrl) * KROWB;
            #pragma unroll
            for (int nb2 = 0; nb2 < 2; ++nb2) {
                uint32_t b4[4];
                lm4t(b4, vH + vrow + (uint32_t)(n0 + nb2 * 16 + vsub) * 2);
                mma16816(oa[nb2 * 2 + 0], a4, b4[0], b4[1]);
                mma16816(oa[nb2 * 2 + 1], a4, b4[2], b4[3]);
            }
        }

        __syncthreads();
        if (t + 2 < 16) {
            pf_v(g_VH + koff + (size_t)(t + 2) * VTROWS * DD_, kvb + (t & 1) * KBUFSZ, tid);
            cp_commit();
        }
    }

    // ---- kh reduction via scratch (dead region: V tiles use only first 9216 of each slot) ----
    float* scr = (float*)(kvb + VHALF);    // [4 grp][16][34] floats = 8704 B < 9216
    const int grp = qh4 * 2 + nh;
    __syncthreads();
    if (kh == 1) {
        #pragma unroll
        for (int j = 0; j < 4; ++j) {
            const int cl = j * 8 + 2 * (lane & 3);
            float* s0 = scr + grp * (16 * 34) + (lane >> 2) * 34 + cl;
            *(float2*)s0 = make_float2(oa[j][0], oa[j][1]);
            *(float2*)(s0 + 8 * 34) = make_float2(oa[j][2], oa[j][3]);
        }
    }
    __syncthreads();
    if (kh == 0 && out_o) {
        const int row0 = q0 + q0o + (lane >> 2);
        #pragma unroll
        for (int j = 0; j < 4; ++j) {
            const int cl = j * 8 + 2 * (lane & 3);
            float2 s0 = *(float2*)(scr + grp * (16 * 34) + (lane >> 2) * 34 + cl);
            float2 s1 = *(float2*)(scr + grp * (16 * 34) + ((lane >> 2) + 8) * 34 + cl);
            float* o0 = out_o + ((size_t)bh * LQ_ + row0) * DD_ + n0 + cl;
            *(float2*)o0 = make_float2(oa[j][0] + s0.x, oa[j][1] + s0.y);
            *(float2*)(o0 + 8 * DD_) = make_float2(oa[j][2] + s1.x, oa[j][3] + s1.y);
        }
    }
}

extern "C" void kernel_launch(void* const* d_in, const int* in_sizes, int n_in,
                              void* d_out, int out_size)
{
    const float* q  = (const float*)d_in[0];
    const float* k  = (const float*)d_in[1];
    const float* v  = (const float*)d_in[2];
    const int*   m  = (const int*)d_in[3];
    const float* qm = (const float*)d_in[4];

    const long long NO = (long long)BH_ * LQ_ * DD_;
    const long long NA = (long long)BH_ * LQ_ * LK_;

    float* out_o = nullptr;
    float* out_a = nullptr;
    if ((long long)out_size >= NO + NA) {
        out_o = (float*)d_out;
        out_a = (float*)d_out + NO;
    } else if ((long long)out_size == NA) {
        out_a = (float*)d_out;
    } else {
        out_o = (float*)d_out;
    }

    cvt_kernel<<<dim3((BH_*LQ_*DD_) / (256 * 4), 3), 256>>>(q, k, v);

    cudaFuncSetAttribute(attn_kernel,
                         cudaFuncAttributeMaxDynamicSharedMemorySize, SM_TOTAL);
    attn_kernel<<<dim3(LQ_ / TQ_, BH_), NT, SM_TOTAL>>>(m, qm, out_o, out_a);
}